// round 2
// baseline (speedup 1.0000x reference)
#include <cuda_runtime.h>
#include <cuda_bf16.h>

#define NN       8192
#define EE       262144
#define IN_NODE  11
#define IN_EDGE  4
#define IN_NF    15   // IN_NODE + IN_EDGE
#define H_NF     4
#define OUT_NF   4
#define EMB_NF   2

// Scratch (static device globals — no runtime allocation allowed)
__device__ float g_agg[NN * IN_EDGE];
__device__ __align__(16) float g_emb[NN * EMB_NF];
__device__ float g_M[IN_NF * EMB_NF];
__device__ float g_c[EMB_NF];

// ---------------------------------------------------------------------------
// k0: zero the aggregation buffer
// ---------------------------------------------------------------------------
__global__ void k_zero() {
    int i = blockIdx.x * blockDim.x + threadIdx.x;
    if (i < NN * IN_EDGE) g_agg[i] = 0.0f;
}

// ---------------------------------------------------------------------------
// k1: segment-sum scatter: agg[row[e]] += edge_attr[e]
// edge_index is int32 [2, E] (JAX x64 disabled downcasts int64->int32);
// row = first E entries.
// ---------------------------------------------------------------------------
__global__ void k_scatter(const int* __restrict__ eidx,
                          const float* __restrict__ eattr) {
    int e = blockIdx.x * blockDim.x + threadIdx.x;
    if (e >= EE) return;
    int r = eidx[e];
    float4 a = *reinterpret_cast<const float4*>(&eattr[e * 4]);
    atomicAdd(&g_agg[r * 4 + 0], a.x);
    atomicAdd(&g_agg[r * 4 + 1], a.y);
    atomicAdd(&g_agg[r * 4 + 2], a.z);
    atomicAdd(&g_agg[r * 4 + 3], a.w);
}

// ---------------------------------------------------------------------------
// k2: fold the affine chain:  emb = x @ (W1 W2 We) + (b1 W2 We + b2 We + be)
// Tiny — one thread.
// ---------------------------------------------------------------------------
__global__ void k_fold(const float* __restrict__ W1, const float* __restrict__ b1,
                       const float* __restrict__ W2, const float* __restrict__ b2,
                       const float* __restrict__ We, const float* __restrict__ be) {
    if (threadIdx.x != 0 || blockIdx.x != 0) return;
    float T[H_NF][EMB_NF];   // W2 @ We
    for (int h = 0; h < H_NF; h++)
        for (int j = 0; j < EMB_NF; j++) {
            float s = 0.0f;
            for (int o = 0; o < OUT_NF; o++)
                s += W2[h * OUT_NF + o] * We[o * EMB_NF + j];
            T[h][j] = s;
        }
    for (int k = 0; k < IN_NF; k++)
        for (int j = 0; j < EMB_NF; j++) {
            float s = 0.0f;
            for (int h = 0; h < H_NF; h++)
                s += W1[k * H_NF + h] * T[h][j];
            g_M[k * EMB_NF + j] = s;
        }
    for (int j = 0; j < EMB_NF; j++) {
        float s = be[j];
        for (int h = 0; h < H_NF; h++) s += b1[h] * T[h][j];
        for (int o = 0; o < OUT_NF; o++) s += b2[o] * We[o * EMB_NF + j];
        g_c[j] = s;
    }
}

// ---------------------------------------------------------------------------
// k3: per-node folded MLP -> emb (to scratch and to d_out tail)
// ---------------------------------------------------------------------------
__global__ void k_mlp(const float* __restrict__ nfeat,
                      float* __restrict__ out_emb) {
    int i = blockIdx.x * blockDim.x + threadIdx.x;
    if (i >= NN) return;
    float in[IN_NF];
#pragma unroll
    for (int k = 0; k < IN_NODE; k++) in[k] = __ldg(&nfeat[i * IN_NODE + k]);
#pragma unroll
    for (int k = 0; k < IN_EDGE; k++) in[IN_NODE + k] = g_agg[i * IN_EDGE + k];
    float e0 = g_c[0], e1 = g_c[1];
#pragma unroll
    for (int k = 0; k < IN_NF; k++) {
        e0 = fmaf(in[k], g_M[k * 2 + 0], e0);
        e1 = fmaf(in[k], g_M[k * 2 + 1], e1);
    }
    g_emb[i * 2 + 0] = e0;
    g_emb[i * 2 + 1] = e1;
    out_emb[i * 2 + 0] = e0;
    out_emb[i * 2 + 1] = e1;
}

// ---------------------------------------------------------------------------
// k4: decode — adj[i][j] = sigmoid(10 * ||emb_i - emb_j||^2 - 1), diag = 0
// One thread = 4 consecutive j (one float4 streaming store).
// emb working set is 64 KB -> L1-resident reuse; kernel is store-bound.
// ---------------------------------------------------------------------------
__device__ __forceinline__ float sig_pair(float2 ei, float ex, float ey) {
    float dx = ei.x - ex;
    float dy = ei.y - ey;
    float d  = fmaf(dx, dx, dy * dy);
    float t  = fmaf(10.0f, d, -1.0f);         // 10*d - 1
    return __fdividef(1.0f, 1.0f + __expf(-t));
}

__global__ void __launch_bounds__(256) k_decode(float* __restrict__ out) {
    unsigned idx = blockIdx.x * 256u + threadIdx.x;   // over N*N/4 exactly
    unsigned i   = idx >> 11;                          // / (N/4 = 2048)
    unsigned j4  = idx & 2047u;
    unsigned jb  = j4 * 4u;

    float2 ei = *reinterpret_cast<const float2*>(&g_emb[i * 2]);
    float4 a  = *reinterpret_cast<const float4*>(&g_emb[jb * 2]);      // j, j+1
    float4 b  = *reinterpret_cast<const float4*>(&g_emb[jb * 2 + 4]);  // j+2, j+3

    float4 r;
    r.x = sig_pair(ei, a.x, a.y);
    r.y = sig_pair(ei, a.z, a.w);
    r.z = sig_pair(ei, b.x, b.y);
    r.w = sig_pair(ei, b.z, b.w);

    unsigned k = i - jb;        // unsigned wrap handles i < jb
    if (k < 4u) {
        if (k == 0u)      r.x = 0.0f;
        else if (k == 1u) r.y = 0.0f;
        else if (k == 2u) r.z = 0.0f;
        else              r.w = 0.0f;
    }

    __stcs(reinterpret_cast<float4*>(&out[(size_t)i * NN + jb]), r);
}

// ---------------------------------------------------------------------------
// launch
// ---------------------------------------------------------------------------
extern "C" void kernel_launch(void* const* d_in, const int* in_sizes, int n_in,
                              void* d_out, int out_size) {
    const float* node_feats = (const float*)d_in[0];
    const int*   edge_index = (const int*)d_in[1];
    const float* edge_attr  = (const float*)d_in[2];
    const float* W1 = (const float*)d_in[3];
    const float* b1 = (const float*)d_in[4];
    const float* W2 = (const float*)d_in[5];
    const float* b2 = (const float*)d_in[6];
    const float* We = (const float*)d_in[7];
    const float* be = (const float*)d_in[8];

    float* out = (float*)d_out;
    // Output layout: adj_pred [N*N] first, node_emb [N*EMB_NF] after.
    float* out_emb = out + (size_t)NN * NN;

    k_zero<<<(NN * IN_EDGE + 255) / 256, 256>>>();
    k_scatter<<<(EE + 255) / 256, 256>>>(edge_index, edge_attr);
    k_fold<<<1, 32>>>(W1, b1, W2, b2, We, be);
    k_mlp<<<(NN + 255) / 256, 256>>>(node_feats, out_emb);
    k_decode<<<(NN * NN / 4) / 256, 256>>>(out);
}

// round 3
// speedup vs baseline: 1.3506x; 1.3506x over previous
#include <cuda_runtime.h>
#include <cuda_bf16.h>

#define NN       8192
#define EE       262144
#define IN_NODE  11
#define H_NF     4
#define OUT_NF   4
#define EMB_NF   2
#define TILE     64
#define NT       (NN / TILE)        // 128 tile rows
#define NBLOCKS  (NT * (NT + 1) / 2)  // 8256 upper-tri tiles

// Scratch (static device global — no runtime allocation allowed)
__device__ __align__(16) float g_emb[NN * EMB_NF];

// ---------------------------------------------------------------------------
// Fold helper: T = W2 @ We  (4x2). ~32 FMA; every thread computes it locally.
// ---------------------------------------------------------------------------
__device__ __forceinline__ void fold_T(const float* __restrict__ W2,
                                       const float* __restrict__ We,
                                       float T[H_NF][EMB_NF]) {
#pragma unroll
    for (int h = 0; h < H_NF; h++)
#pragma unroll
        for (int j = 0; j < EMB_NF; j++) {
            float s = 0.0f;
#pragma unroll
            for (int o = 0; o < OUT_NF; o++)
                s = fmaf(__ldg(&W2[h * OUT_NF + o]), __ldg(&We[o * EMB_NF + j]), s);
            T[h][j] = s;
        }
}

// ---------------------------------------------------------------------------
// k1: per-node base embedding:
//   emb_i = (b1 W2 We + b2 We + be) + node_feats_i @ (W1[0:11] W2 We)
// ---------------------------------------------------------------------------
__global__ void k_init(const float* __restrict__ nf,
                       const float* __restrict__ W1, const float* __restrict__ b1,
                       const float* __restrict__ W2, const float* __restrict__ b2,
                       const float* __restrict__ We, const float* __restrict__ be) {
    int i = blockIdx.x * blockDim.x + threadIdx.x;
    if (i >= NN) return;
    float T[H_NF][EMB_NF];
    fold_T(W2, We, T);
    float c0 = __ldg(&be[0]), c1 = __ldg(&be[1]);
#pragma unroll
    for (int h = 0; h < H_NF; h++) {
        float bh = __ldg(&b1[h]);
        c0 = fmaf(bh, T[h][0], c0);
        c1 = fmaf(bh, T[h][1], c1);
    }
#pragma unroll
    for (int o = 0; o < OUT_NF; o++) {
        float bo = __ldg(&b2[o]);
        c0 = fmaf(bo, __ldg(&We[o * EMB_NF + 0]), c0);
        c1 = fmaf(bo, __ldg(&We[o * EMB_NF + 1]), c1);
    }
#pragma unroll
    for (int k = 0; k < IN_NODE; k++) {
        float x = __ldg(&nf[i * IN_NODE + k]);
        float m0 = 0.0f, m1 = 0.0f;
#pragma unroll
        for (int h = 0; h < H_NF; h++) {
            float w = __ldg(&W1[k * H_NF + h]);
            m0 = fmaf(w, T[h][0], m0);
            m1 = fmaf(w, T[h][1], m1);
        }
        c0 = fmaf(x, m0, c0);
        c1 = fmaf(x, m1, c1);
    }
    g_emb[i * 2 + 0] = c0;
    g_emb[i * 2 + 1] = c1;
}

// ---------------------------------------------------------------------------
// k2: edge scatter directly in embedding space:
//   emb[row[e]] += edge_attr[e] @ (W1[11:15] W2 We)    (2 atomics per edge)
// edge_index is int32 [2, E]; row = first E entries.
// ---------------------------------------------------------------------------
__global__ void k_scatter(const int* __restrict__ eidx,
                          const float* __restrict__ eattr,
                          const float* __restrict__ W1,
                          const float* __restrict__ W2,
                          const float* __restrict__ We) {
    int e = blockIdx.x * blockDim.x + threadIdx.x;
    if (e >= EE) return;
    float T[H_NF][EMB_NF];
    fold_T(W2, We, T);
    float4 a = __ldg(reinterpret_cast<const float4*>(&eattr[e * 4]));
    float av[4] = {a.x, a.y, a.z, a.w};
    float c0 = 0.0f, c1 = 0.0f;
#pragma unroll
    for (int k = 0; k < 4; k++) {
        float m0 = 0.0f, m1 = 0.0f;
#pragma unroll
        for (int h = 0; h < H_NF; h++) {
            float w = __ldg(&W1[(IN_NODE + k) * H_NF + h]);
            m0 = fmaf(w, T[h][0], m0);
            m1 = fmaf(w, T[h][1], m1);
        }
        c0 = fmaf(av[k], m0, c0);
        c1 = fmaf(av[k], m1, c1);
    }
    int r = __ldg(&eidx[e]);
    atomicAdd(&g_emb[r * 2 + 0], c0);
    atomicAdd(&g_emb[r * 2 + 1], c1);
}

// ---------------------------------------------------------------------------
// k3: symmetric tiled decode.
// Block b -> upper-tri tile (I,J), J >= I. Computes 64x64 sigmoid tile once,
// stores it direct (coalesced float4 streaming) and, for off-diagonal tiles,
// stores the transpose via smem (also coalesced). Halves the MUFU work.
// Blocks 0..15 additionally emit node_emb to the output tail.
// ---------------------------------------------------------------------------
__device__ __forceinline__ float sig_pair(float2 ei, float ex, float ey) {
    float dx = ei.x - ex;
    float dy = ei.y - ey;
    float d  = fmaf(dx, dx, dy * dy);
    float t  = fmaf(10.0f, d, -1.0f);
    return __fdividef(1.0f, 1.0f + __expf(-t));
}

__global__ void __launch_bounds__(256) k_decode(float* __restrict__ out,
                                                float* __restrict__ out_emb) {
    __shared__ float sm[TILE][TILE + 1];
    int b = blockIdx.x;

    // emit node_emb (16 blocks x 256 threads x 1 float4 = 16384 floats)
    if (b < 16) {
        int t = b * 256 + threadIdx.x;
        reinterpret_cast<float4*>(out_emb)[t] =
            reinterpret_cast<const float4*>(g_emb)[t];
    }

    // map linear block index -> upper-triangular tile (I, J)
    float bf = (float)b;
    const float tnp1 = 2.0f * NT + 1.0f;   // 257
    int I = (int)(0.5f * (tnp1 - sqrtf(tnp1 * tnp1 - 8.0f * bf)));
    if (I < 0) I = 0;
    if (I > NT - 1) I = NT - 1;
    while ((I + 1) * NT - (I + 1) * I / 2 <= b) I++;   // off(I+1) <= b
    while (I * NT - I * (I - 1) / 2 > b) I--;          // off(I)   >  b
    int J = I + (b - (I * NT - I * (I - 1) / 2));
    bool diag = (I == J);

    int i0 = I * TILE, j0 = J * TILE;
    int tj = threadIdx.x & 15;   // 0..15 (4 j's each)
    int ti = threadIdx.x >> 4;   // 0..15 row group
    int jb = tj * 4;

    // this thread's 4 j-embeddings (fixed across passes)
    const float* eJ = &g_emb[(j0 + jb) * 2];
    float4 ea = *reinterpret_cast<const float4*>(eJ);       // j, j+1
    float4 eb = *reinterpret_cast<const float4*>(eJ + 4);   // j+2, j+3

#pragma unroll
    for (int p = 0; p < 4; p++) {
        int il = ti + p * 16;
        float2 ei = *reinterpret_cast<const float2*>(&g_emb[(i0 + il) * 2]);
        float4 r;
        r.x = sig_pair(ei, ea.x, ea.y);
        r.y = sig_pair(ei, ea.z, ea.w);
        r.z = sig_pair(ei, eb.x, eb.y);
        r.w = sig_pair(ei, eb.z, eb.w);
        if (diag) {
            unsigned k = (unsigned)il - (unsigned)jb;
            if (k < 4u) {
                if (k == 0u)      r.x = 0.0f;
                else if (k == 1u) r.y = 0.0f;
                else if (k == 2u) r.z = 0.0f;
                else              r.w = 0.0f;
            }
        }
        __stcs(reinterpret_cast<float4*>(&out[(size_t)(i0 + il) * NN + j0 + jb]), r);
        if (!diag) {
            sm[jb + 0][il] = r.x;
            sm[jb + 1][il] = r.y;
            sm[jb + 2][il] = r.z;
            sm[jb + 3][il] = r.w;
        }
    }

    if (!diag) {
        __syncthreads();
#pragma unroll
        for (int p = 0; p < 4; p++) {
            int jr = ti + p * 16;
            int ib = tj * 4;
            float4 w;
            w.x = sm[jr][ib + 0];
            w.y = sm[jr][ib + 1];
            w.z = sm[jr][ib + 2];
            w.w = sm[jr][ib + 3];
            __stcs(reinterpret_cast<float4*>(&out[(size_t)(j0 + jr) * NN + i0 + ib]), w);
        }
    }
}

// ---------------------------------------------------------------------------
// launch
// ---------------------------------------------------------------------------
extern "C" void kernel_launch(void* const* d_in, const int* in_sizes, int n_in,
                              void* d_out, int out_size) {
    const float* node_feats = (const float*)d_in[0];
    const int*   edge_index = (const int*)d_in[1];
    const float* edge_attr  = (const float*)d_in[2];
    const float* W1 = (const float*)d_in[3];
    const float* b1 = (const float*)d_in[4];
    const float* W2 = (const float*)d_in[5];
    const float* b2 = (const float*)d_in[6];
    const float* We = (const float*)d_in[7];
    const float* be = (const float*)d_in[8];

    float* out = (float*)d_out;
    float* out_emb = out + (size_t)NN * NN;   // adj [N*N] then node_emb [N*2]

    k_init<<<(NN + 255) / 256, 256>>>(node_feats, W1, b1, W2, b2, We, be);
    k_scatter<<<(EE + 255) / 256, 256>>>(edge_index, edge_attr, W1, W2, We);
    k_decode<<<NBLOCKS, 256>>>(out, out_emb);
}

// round 4
// speedup vs baseline: 1.3746x; 1.0178x over previous
#include <cuda_runtime.h>
#include <cuda_bf16.h>

#define NN       8192
#define EE       262144
#define IN_NODE  11
#define H_NF     4
#define OUT_NF   4
#define EMB_NF   2
#define TILE     64
#define NT       (NN / TILE)          // 128 tile rows
#define NBLOCKS  (NT * (NT + 1) / 2)  // 8256 upper-tri tiles

#define SCAT_BLK (EE / 256)           // 1024 scatter blocks
#define INIT_BLK (NN / 256)           // 32 init blocks

// Scratch (static device global — no runtime allocation allowed)
__device__ __align__(16) float g_emb[NN * EMB_NF];

// ---------------------------------------------------------------------------
// k0: zero the embedding accumulator (makes the call state-independent)
// ---------------------------------------------------------------------------
__global__ void k_zero() {
    int i = blockIdx.x * blockDim.x + threadIdx.x;   // 4096 float4
    reinterpret_cast<float4*>(g_emb)[i] = make_float4(0.f, 0.f, 0.f, 0.f);
}

// ---------------------------------------------------------------------------
// Fold helper: T = W2 @ We  (4x2). ~32 FMA; every thread computes it locally.
// ---------------------------------------------------------------------------
__device__ __forceinline__ void fold_T(const float* __restrict__ W2,
                                       const float* __restrict__ We,
                                       float T[H_NF][EMB_NF]) {
#pragma unroll
    for (int h = 0; h < H_NF; h++)
#pragma unroll
        for (int j = 0; j < EMB_NF; j++) {
            float s = 0.0f;
#pragma unroll
            for (int o = 0; o < OUT_NF; o++)
                s = fmaf(__ldg(&W2[h * OUT_NF + o]), __ldg(&We[o * EMB_NF + j]), s);
            T[h][j] = s;
        }
}

// ---------------------------------------------------------------------------
// k1 (fused): blocks [0, SCAT_BLK) scatter edge contributions,
//             blocks [SCAT_BLK, SCAT_BLK+INIT_BLK) add per-node base emb.
// Both paths atomicAdd into the pre-zeroed g_emb -> no ordering needed.
// ---------------------------------------------------------------------------
__global__ void __launch_bounds__(256) k_fused(
        const int* __restrict__ eidx, const float* __restrict__ eattr,
        const float* __restrict__ nf,
        const float* __restrict__ W1, const float* __restrict__ b1,
        const float* __restrict__ W2, const float* __restrict__ b2,
        const float* __restrict__ We, const float* __restrict__ be) {
    int b = blockIdx.x;
    float T[H_NF][EMB_NF];
    fold_T(W2, We, T);

    if (b < SCAT_BLK) {
        // --- edge scatter: emb[row[e]] += edge_attr[e] @ (W1[11:15] W2 We) ---
        int e = b * 256 + threadIdx.x;
        float4 a = __ldg(reinterpret_cast<const float4*>(&eattr[e * 4]));
        float av[4] = {a.x, a.y, a.z, a.w};
        float c0 = 0.0f, c1 = 0.0f;
#pragma unroll
        for (int k = 0; k < 4; k++) {
            float m0 = 0.0f, m1 = 0.0f;
#pragma unroll
            for (int h = 0; h < H_NF; h++) {
                float w = __ldg(&W1[(IN_NODE + k) * H_NF + h]);
                m0 = fmaf(w, T[h][0], m0);
                m1 = fmaf(w, T[h][1], m1);
            }
            c0 = fmaf(av[k], m0, c0);
            c1 = fmaf(av[k], m1, c1);
        }
        int r = __ldg(&eidx[e]);
        atomicAdd(&g_emb[r * 2 + 0], c0);
        atomicAdd(&g_emb[r * 2 + 1], c1);
    } else {
        // --- base emb: bias chain + node_feats_i @ (W1[0:11] W2 We) ---
        int i = (b - SCAT_BLK) * 256 + threadIdx.x;
        float c0 = __ldg(&be[0]), c1 = __ldg(&be[1]);
#pragma unroll
        for (int h = 0; h < H_NF; h++) {
            float bh = __ldg(&b1[h]);
            c0 = fmaf(bh, T[h][0], c0);
            c1 = fmaf(bh, T[h][1], c1);
        }
#pragma unroll
        for (int o = 0; o < OUT_NF; o++) {
            float bo = __ldg(&b2[o]);
            c0 = fmaf(bo, __ldg(&We[o * EMB_NF + 0]), c0);
            c1 = fmaf(bo, __ldg(&We[o * EMB_NF + 1]), c1);
        }
#pragma unroll
        for (int k = 0; k < IN_NODE; k++) {
            float x = __ldg(&nf[i * IN_NODE + k]);
            float m0 = 0.0f, m1 = 0.0f;
#pragma unroll
            for (int h = 0; h < H_NF; h++) {
                float w = __ldg(&W1[k * H_NF + h]);
                m0 = fmaf(w, T[h][0], m0);
                m1 = fmaf(w, T[h][1], m1);
            }
            c0 = fmaf(x, m0, c0);
            c1 = fmaf(x, m1, c1);
        }
        atomicAdd(&g_emb[i * 2 + 0], c0);
        atomicAdd(&g_emb[i * 2 + 1], c1);
    }
}

// ---------------------------------------------------------------------------
// k2: symmetric tiled decode.
// Block b -> upper-tri tile (I,J), J >= I. Computes 64x64 sigmoid tile once,
// stores it direct (coalesced float4 streaming) and, for off-diagonal tiles,
// stores the transpose via smem (also coalesced). Halves the MUFU work.
// Blocks 0..15 additionally emit node_emb to the output tail.
// ---------------------------------------------------------------------------
__device__ __forceinline__ float sig_pair(float2 ei, float ex, float ey) {
    float dx = ei.x - ex;
    float dy = ei.y - ey;
    float d  = fmaf(dx, dx, dy * dy);
    float t  = fmaf(10.0f, d, -1.0f);
    return __fdividef(1.0f, 1.0f + __expf(-t));
}

__global__ void __launch_bounds__(256) k_decode(float* __restrict__ out,
                                                float* __restrict__ out_emb) {
    __shared__ float sm[TILE][TILE + 1];
    int b = blockIdx.x;

    // emit node_emb (16 blocks x 256 threads x 1 float4 = 16384 floats)
    if (b < 16) {
        int t = b * 256 + threadIdx.x;
        reinterpret_cast<float4*>(out_emb)[t] =
            reinterpret_cast<const float4*>(g_emb)[t];
    }

    // map linear block index -> upper-triangular tile (I, J)
    float bf = (float)b;
    const float tnp1 = 2.0f * NT + 1.0f;   // 257
    int I = (int)(0.5f * (tnp1 - sqrtf(tnp1 * tnp1 - 8.0f * bf)));
    if (I < 0) I = 0;
    if (I > NT - 1) I = NT - 1;
    while ((I + 1) * NT - (I + 1) * I / 2 <= b) I++;   // off(I+1) <= b
    while (I * NT - I * (I - 1) / 2 > b) I--;          // off(I)   >  b
    int J = I + (b - (I * NT - I * (I - 1) / 2));
    bool diag = (I == J);

    int i0 = I * TILE, j0 = J * TILE;
    int tj = threadIdx.x & 15;   // 0..15 (4 j's each)
    int ti = threadIdx.x >> 4;   // 0..15 row group
    int jb = tj * 4;

    // this thread's 4 j-embeddings (fixed across passes)
    const float* eJ = &g_emb[(j0 + jb) * 2];
    float4 ea = *reinterpret_cast<const float4*>(eJ);       // j, j+1
    float4 eb = *reinterpret_cast<const float4*>(eJ + 4);   // j+2, j+3

#pragma unroll
    for (int p = 0; p < 4; p++) {
        int il = ti + p * 16;
        float2 ei = *reinterpret_cast<const float2*>(&g_emb[(i0 + il) * 2]);
        float4 r;
        r.x = sig_pair(ei, ea.x, ea.y);
        r.y = sig_pair(ei, ea.z, ea.w);
        r.z = sig_pair(ei, eb.x, eb.y);
        r.w = sig_pair(ei, eb.z, eb.w);
        if (diag) {
            unsigned k = (unsigned)il - (unsigned)jb;
            if (k < 4u) {
                if (k == 0u)      r.x = 0.0f;
                else if (k == 1u) r.y = 0.0f;
                else if (k == 2u) r.z = 0.0f;
                else              r.w = 0.0f;
            }
        }
        __stcs(reinterpret_cast<float4*>(&out[(size_t)(i0 + il) * NN + j0 + jb]), r);
        if (!diag) {
            sm[jb + 0][il] = r.x;
            sm[jb + 1][il] = r.y;
            sm[jb + 2][il] = r.z;
            sm[jb + 3][il] = r.w;
        }
    }

    if (!diag) {
        __syncthreads();
#pragma unroll
        for (int p = 0; p < 4; p++) {
            int jr = ti + p * 16;
            int ib = tj * 4;
            float4 w;
            w.x = sm[jr][ib + 0];
            w.y = sm[jr][ib + 1];
            w.z = sm[jr][ib + 2];
            w.w = sm[jr][ib + 3];
            __stcs(reinterpret_cast<float4*>(&out[(size_t)(j0 + jr) * NN + i0 + ib]), w);
        }
    }
}

// ---------------------------------------------------------------------------
// launch
// ---------------------------------------------------------------------------
extern "C" void kernel_launch(void* const* d_in, const int* in_sizes, int n_in,
                              void* d_out, int out_size) {
    const float* node_feats = (const float*)d_in[0];
    const int*   edge_index = (const int*)d_in[1];
    const float* edge_attr  = (const float*)d_in[2];
    const float* W1 = (const float*)d_in[3];
    const float* b1 = (const float*)d_in[4];
    const float* W2 = (const float*)d_in[5];
    const float* b2 = (const float*)d_in[6];
    const float* We = (const float*)d_in[7];
    const float* be = (const float*)d_in[8];

    float* out = (float*)d_out;
    float* out_emb = out + (size_t)NN * NN;   // adj [N*N] then node_emb [N*2]

    k_zero<<<16, 256>>>();
    k_fused<<<SCAT_BLK + INIT_BLK, 256>>>(edge_index, edge_attr, node_feats,
                                          W1, b1, W2, b2, We, be);
    k_decode<<<NBLOCKS, 256>>>(out, out_emb);
}